// round 14
// baseline (speedup 1.0000x reference)
#include <cuda_runtime.h>
#include <cuda_fp16.h>
#include <math.h>

#define NN 50000
#define NE 600000
#define FDIM 128
#define SCAN_EPB 1024
#define SCAN_NBLK ((NN + SCAN_EPB - 1) / SCAN_EPB)   // 49

#define GEMM_BLOCKS ((NN + 127) / 128)               // 391
#define SW_PITCH 136
#define SA_PITCH 68
#define GEMM_SMEM_BYTES ((128 * SW_PITCH + 128 * SA_PITCH) * 4)   // 104448

// ---------------- scratch (static device globals; zero-initialized) ----------------
// INVARIANT: g_deg and g_lb_flag are zero at kernel_launch entry; every launch
// restores them to zero (scan re-zeros deg after reading; fill re-zeros flags).
__device__ int     g_deg[NN + 4];
__device__ float   g_dinv[NN];
__device__ int     g_rowptr[NN + 1];
__device__ int     g_rank[NE];
__device__ int     g_col[NE];
__device__ int     g_lb_flag[SCAN_NBLK];
__device__ int     g_lb_agg [SCAN_NBLK];
__device__ int     g_lb_incl[SCAN_NBLK];
__device__ __half2 g_h1h[(size_t)NN * 64];    // h1 = x@W1 in fp16 (256B per node)
__device__ float   g_t [(size_t)NN * 2];      // PRE-SCALED: dinv[n] * ((relu(agg)+b1)@W2)

// ---------------- GEMM1 (tf32 tensor cores): h1 = x @ W1 -> fp16 ----------------
__device__ __forceinline__ unsigned f2tf32(float f) {
    unsigned u;
    asm("cvt.rna.tf32.f32 %0, %1;" : "=r"(u) : "f"(f));
    return u;
}

__global__ void __launch_bounds__(256, 2)
gemm1_tf32_kernel(const float* __restrict__ A, const float* __restrict__ W) {
    extern __shared__ unsigned smem_u[];
    unsigned* Ws = smem_u;                      // [128][SW_PITCH]
    unsigned* As = smem_u + 128 * SW_PITCH;     // [128][SA_PITCH]

    const int tid  = threadIdx.x;
    const int lane = tid & 31;
    const int wid  = tid >> 5;
    const int g    = lane >> 2;
    const int t    = lane & 3;
    const int wm   = (wid & 3) * 32;
    const int wn   = (wid >> 2) * 64;
    const int block_row = blockIdx.x * 128;

    #pragma unroll
    for (int i = 0; i < 16; i++) {
        int idx  = tid + i * 256;
        int row  = idx >> 5;
        int col4 = (idx & 31) * 4;
        float4 v = *(const float4*)&W[(size_t)row * 128 + col4];
        unsigned* p = &Ws[row * SW_PITCH + col4];
        p[0] = f2tf32(v.x); p[1] = f2tf32(v.y); p[2] = f2tf32(v.z); p[3] = f2tf32(v.w);
    }

    float acc[2][8][4];
    #pragma unroll
    for (int mt = 0; mt < 2; mt++)
        #pragma unroll
        for (int j = 0; j < 8; j++)
            #pragma unroll
            for (int q = 0; q < 4; q++) acc[mt][j][q] = 0.f;

    #pragma unroll
    for (int kc = 0; kc < 2; kc++) {
        __syncthreads();
        #pragma unroll
        for (int i = 0; i < 8; i++) {
            int idx  = tid + i * 256;
            int row  = idx >> 4;
            int col4 = (idx & 15) * 4;
            int grow = block_row + row;
            float4 v = (grow < NN) ? *(const float4*)&A[(size_t)grow * 128 + kc * 64 + col4]
                                   : make_float4(0.f, 0.f, 0.f, 0.f);
            unsigned* p = &As[row * SA_PITCH + col4];
            p[0] = f2tf32(v.x); p[1] = f2tf32(v.y); p[2] = f2tf32(v.z); p[3] = f2tf32(v.w);
        }
        __syncthreads();

        #pragma unroll
        for (int kk = 0; kk < 8; kk++) {
            int k0 = kk * 8;
            unsigned a[2][4];
            #pragma unroll
            for (int mt = 0; mt < 2; mt++) {
                int r0 = wm + mt * 16;
                a[mt][0] = As[(r0 + g    ) * SA_PITCH + k0 + t    ];
                a[mt][1] = As[(r0 + g + 8) * SA_PITCH + k0 + t    ];
                a[mt][2] = As[(r0 + g    ) * SA_PITCH + k0 + t + 4];
                a[mt][3] = As[(r0 + g + 8) * SA_PITCH + k0 + t + 4];
            }
            #pragma unroll
            for (int j = 0; j < 8; j++) {
                int n0 = wn + j * 8;
                unsigned b0 = Ws[(kc * 64 + k0 + t    ) * SW_PITCH + n0 + g];
                unsigned b1 = Ws[(kc * 64 + k0 + t + 4) * SW_PITCH + n0 + g];
                #pragma unroll
                for (int mt = 0; mt < 2; mt++) {
                    asm volatile(
                        "mma.sync.aligned.m16n8k8.row.col.f32.tf32.tf32.f32 "
                        "{%0,%1,%2,%3}, {%4,%5,%6,%7}, {%8,%9}, {%0,%1,%2,%3};\n"
                        : "+f"(acc[mt][j][0]), "+f"(acc[mt][j][1]),
                          "+f"(acc[mt][j][2]), "+f"(acc[mt][j][3])
                        : "r"(a[mt][0]), "r"(a[mt][1]), "r"(a[mt][2]), "r"(a[mt][3]),
                          "r"(b0), "r"(b1));
                }
            }
        }
    }

    #pragma unroll
    for (int mt = 0; mt < 2; mt++) {
        #pragma unroll
        for (int j = 0; j < 8; j++) {
            int col = wn + j * 8 + 2 * t;
            int r0  = block_row + wm + mt * 16 + g;
            int r1  = r0 + 8;
            if (r0 < NN)
                g_h1h[(size_t)r0 * 64 + (col >> 1)] = __floats2half2_rn(acc[mt][j][0], acc[mt][j][1]);
            if (r1 < NN)
                g_h1h[(size_t)r1 * 64 + (col >> 1)] = __floats2half2_rn(acc[mt][j][2], acc[mt][j][3]);
        }
    }
}

// ---------------- fallback SIMT GEMM ----------------
__global__ void gemm1_kernel(const float* __restrict__ A, const float* __restrict__ W) {
    __shared__ float Asb[16][128];
    __shared__ float Bsb[16][128];
    const int block_row = blockIdx.x * 128;
    const int tid  = threadIdx.x;
    const int tcol = tid & 15;
    const int trow = tid >> 4;

    float acc[8][8];
    #pragma unroll
    for (int i = 0; i < 8; i++)
        #pragma unroll
        for (int j = 0; j < 8; j++) acc[i][j] = 0.f;

    for (int k0 = 0; k0 < 128; k0 += 16) {
        #pragma unroll
        for (int l = 0; l < 2; l++) {
            int f  = tid * 2 + l;
            int r  = f >> 2;
            int kq = (f & 3) * 4;
            int grow = block_row + r;
            float4 v = (grow < NN) ? *(const float4*)&A[(size_t)grow * 128 + k0 + kq]
                                   : make_float4(0.f, 0.f, 0.f, 0.f);
            Asb[kq + 0][r] = v.x; Asb[kq + 1][r] = v.y;
            Asb[kq + 2][r] = v.z; Asb[kq + 3][r] = v.w;
        }
        #pragma unroll
        for (int l = 0; l < 2; l++) {
            int f  = tid * 2 + l;
            int r  = f >> 5;
            int cq = (f & 31) * 4;
            *(float4*)&Bsb[r][cq] = *(const float4*)&W[(size_t)(k0 + r) * 128 + cq];
        }
        __syncthreads();
        #pragma unroll
        for (int kk = 0; kk < 16; kk++) {
            float a[8], b[8];
            #pragma unroll
            for (int i = 0; i < 8; i += 4) *(float4*)&a[i] = *(float4*)&Asb[kk][trow * 8 + i];
            #pragma unroll
            for (int j = 0; j < 8; j += 4) *(float4*)&b[j] = *(float4*)&Bsb[kk][tcol * 8 + j];
            #pragma unroll
            for (int i = 0; i < 8; i++)
                #pragma unroll
                for (int j = 0; j < 8; j++) acc[i][j] += a[i] * b[j];
        }
        __syncthreads();
    }
    #pragma unroll
    for (int i = 0; i < 8; i++) {
        int grow = block_row + trow * 8 + i;
        if (grow < NN) {
            #pragma unroll
            for (int j = 0; j < 8; j += 2)
                g_h1h[(size_t)grow * 64 + (tcol * 8 + j) / 2] =
                    __floats2half2_rn(acc[i][j], acc[i][j + 1]);
        }
    }
}

// ---------------- host-side stream/event + gemm config ----------
static cudaStream_t g_side = nullptr;
static cudaEvent_t  g_evFork = nullptr, g_evJoin = nullptr;
static bool g_tf32_ok = false;
namespace {
struct InitOnce {
    InitOnce() {
        if (cudaStreamCreateWithFlags(&g_side, cudaStreamNonBlocking) != cudaSuccess) g_side = nullptr;
        if (cudaEventCreateWithFlags(&g_evFork, cudaEventDisableTiming) != cudaSuccess) g_evFork = nullptr;
        if (cudaEventCreateWithFlags(&g_evJoin, cudaEventDisableTiming) != cudaSuccess) g_evJoin = nullptr;
        if (!g_evFork || !g_evJoin) g_side = nullptr;
        g_tf32_ok = (cudaFuncSetAttribute(gemm1_tf32_kernel,
                        cudaFuncAttributeMaxDynamicSharedMemorySize,
                        GEMM_SMEM_BYTES) == cudaSuccess);
    }
};
static InitOnce g_initOnce;
}

// ---------------- degree count + per-edge rank ----------------
__global__ void count_deg_kernel(const int* __restrict__ dst) {
    int e = blockIdx.x * blockDim.x + threadIdx.x;
    if (e < NE) g_rank[e] = atomicAdd(&g_deg[dst[e]], 1);
}

// ---------------- single-kernel decoupled-lookback scan (re-zeros g_deg) ----------------
__global__ void scan_lookback_kernel() {
    __shared__ int ws[8];
    __shared__ int s_tot;
    __shared__ int s_ex;
    const int tid  = threadIdx.x;
    const int lane = tid & 31, warp = tid >> 5;
    const int b    = blockIdx.x;
    const int base = b * SCAN_EPB + tid * 4;

    int4 v = make_int4(0, 0, 0, 0);
    if (base + 3 < NN) {
        v = *(const int4*)&g_deg[base];
        *(int4*)&g_deg[base] = make_int4(0, 0, 0, 0);
    } else {
        if (base     < NN) { v.x = g_deg[base];     g_deg[base]     = 0; }
        if (base + 1 < NN) { v.y = g_deg[base + 1]; g_deg[base + 1] = 0; }
        if (base + 2 < NN) { v.z = g_deg[base + 2]; g_deg[base + 2] = 0; }
        if (base + 3 < NN) { v.w = g_deg[base + 3]; g_deg[base + 3] = 0; }
    }
    int s = v.x + v.y + v.z + v.w;

    int sc = s;
    #pragma unroll
    for (int off = 1; off < 32; off <<= 1) {
        int n = __shfl_up_sync(0xffffffff, sc, off);
        if (lane >= off) sc += n;
    }
    if (lane == 31) ws[warp] = sc;
    __syncthreads();
    if (warp == 0 && lane < 8) {
        int wv = ws[lane];
        int wsc = wv;
        #pragma unroll
        for (int off = 1; off < 8; off <<= 1) {
            int n = __shfl_up_sync(0x000000ff, wsc, off);
            if (lane >= off) wsc += n;
        }
        if (lane == 7) s_tot = wsc;
        ws[lane] = wsc - wv;
    }
    __syncthreads();
    int ex_local = (sc - s) + ws[warp];
    int tot = s_tot;

    if (tid == 0) {
        g_lb_agg[b] = tot;
        __threadfence();
        if (b == 0) {
            g_lb_incl[0] = tot;
            __threadfence();
            *(volatile int*)&g_lb_flag[0] = 2;
            s_ex = 0;
            g_rowptr[0] = 0;
        } else {
            *(volatile int*)&g_lb_flag[b] = 1;
        }
    }

    if (b > 0 && warp == 0) {
        int ex = 0;
        int base_p = b - 1;
        while (true) {
            int p = base_p - lane;
            int f = 0, val = 0;
            if (p >= 0) {
                volatile int* fp = (volatile int*)&g_lb_flag[p];
                do { f = *fp; } while (f == 0);
                __threadfence();
                val = (f == 2) ? *(volatile int*)&g_lb_incl[p]
                               : *(volatile int*)&g_lb_agg[p];
            }
            unsigned m2 = __ballot_sync(0xffffffff, (p >= 0) && (f == 2));
            if (m2) {
                int stop = __ffs(m2) - 1;
                int contrib = (lane <= stop) ? val : 0;
                #pragma unroll
                for (int off = 16; off > 0; off >>= 1)
                    contrib += __shfl_xor_sync(0xffffffff, contrib, off);
                ex += contrib;
                break;
            } else {
                int contrib = (p >= 0) ? val : 0;
                #pragma unroll
                for (int off = 16; off > 0; off >>= 1)
                    contrib += __shfl_xor_sync(0xffffffff, contrib, off);
                ex += contrib;
                base_p -= 32;
                if (base_p < 0) break;
            }
        }
        if (lane == 0) {
            g_lb_incl[b] = ex + tot;
            __threadfence();
            *(volatile int*)&g_lb_flag[b] = 2;
            s_ex = ex;
        }
    }
    __syncthreads();

    int run = s_ex + ex_local;
    #pragma unroll
    for (int j = 0; j < 4; j++) {
        int idx = base + j;
        if (idx < NN) {
            int d = (j == 0) ? v.x : (j == 1) ? v.y : (j == 2) ? v.z : v.w;
            g_dinv[idx] = rsqrtf((float)(d + 1));
            run += d;
            g_rowptr[idx + 1] = run;
        }
    }
}

// ---------------- CSR fill (atomic-free) + flag re-zero ----------------
__global__ void fill_csr_kernel(const int* __restrict__ src, const int* __restrict__ dst) {
    int e = blockIdx.x * blockDim.x + threadIdx.x;
    if (e < NE) {
        int d = dst[e];
        g_col[g_rowptr[d] + g_rank[e]] = src[e];
    }
    if (blockIdx.x == 0 && threadIdx.x < SCAN_NBLK) g_lb_flag[threadIdx.x] = 0;
}

// ---------------- Fused layer-1 agg + bias + relu + W2 ----------------
// 2 edges per warp iteration: lanes 0-15 -> item k, lanes 16-31 -> item k+1.
// Each lane gathers uint4 (16B = 8 features). Virtual item 0 = self loop.
// g_t stored PRE-SCALED by dinv.
__global__ void agg1_fused_kernel(const float* __restrict__ b1, const float* __restrict__ W2) {
    int node = blockIdx.x * (blockDim.x >> 5) + (threadIdx.x >> 5);
    if (node >= NN) return;
    int lane = threadIdx.x & 31;
    int pair = lane >> 4;        // which item of the pair
    int fl   = lane & 15;        // feature group: features fl*8 .. fl*8+7

    // per-lane weights in registers (b1: 8 floats, W2: 8x2 floats), L1-cached global
    float rb1[8];
    float rw2[16];
    {
        const float4* pb = (const float4*)&b1[fl * 8];
        float4 b0 = pb[0], b4 = pb[1];
        rb1[0]=b0.x; rb1[1]=b0.y; rb1[2]=b0.z; rb1[3]=b0.w;
        rb1[4]=b4.x; rb1[5]=b4.y; rb1[6]=b4.z; rb1[7]=b4.w;
        const float4* pw = (const float4*)&W2[fl * 16];
        #pragma unroll
        for (int i = 0; i < 4; i++) {
            float4 wv = pw[i];
            rw2[i*4+0]=wv.x; rw2[i*4+1]=wv.y; rw2[i*4+2]=wv.z; rw2[i*4+3]=wv.w;
        }
    }

    float di = g_dinv[node];
    float w0 = di * di;

    float acc[8];
    #pragma unroll
    for (int q = 0; q < 8; q++) acc[q] = 0.f;

    int beg = g_rowptr[node];
    int total = g_rowptr[node + 1] - beg + 1;   // +1 for self item (k=0)

    for (int k0 = 0; k0 < total; k0 += 2) {
        int k = k0 + pair;
        if (k < total) {
            int   cidx;
            float w;
            if (k == 0) { cidx = node; w = w0; }
            else        { cidx = g_col[beg + k - 1]; w = g_dinv[cidx] * di; }
            uint4 r = *(const uint4*)&g_h1h[(size_t)cidx * 64 + fl * 4];
            float2 p0 = __half22float2(*(__half2*)&r.x);
            float2 p1 = __half22float2(*(__half2*)&r.y);
            float2 p2 = __half22float2(*(__half2*)&r.z);
            float2 p3 = __half22float2(*(__half2*)&r.w);
            acc[0] += w * p0.x; acc[1] += w * p0.y;
            acc[2] += w * p1.x; acc[3] += w * p1.y;
            acc[4] += w * p2.x; acc[5] += w * p2.y;
            acc[6] += w * p3.x; acc[7] += w * p3.y;
        }
    }

    // merge the two halves: lanes L and L^16 hold partial sums of the same features
    #pragma unroll
    for (int q = 0; q < 8; q++)
        acc[q] += __shfl_xor_sync(0xffffffff, acc[q], 16);

    // bias + relu + project to 2 outputs (both halves compute identically)
    float t0 = 0.f, t1 = 0.f;
    #pragma unroll
    for (int q = 0; q < 8; q++) {
        float v = fmaxf(acc[q] + rb1[q], 0.f);
        t0 += v * rw2[q * 2 + 0];
        t1 += v * rw2[q * 2 + 1];
    }
    #pragma unroll
    for (int off = 8; off > 0; off >>= 1) {
        t0 += __shfl_xor_sync(0xffffffff, t0, off);
        t1 += __shfl_xor_sync(0xffffffff, t1, off);
    }
    if (lane == 0)
        *(float2*)&g_t[(size_t)node * 2] = make_float2(di * t0, di * t1);
}

// ---------------- Layer-2 aggregation: WARP per node, lanes split edges ----------------
// out[n] = di * (sum_{s in N(n)} tsc[s] + tsc[n]) + b2,  tsc = dinv*t
// (di * tsc[n] = di^2 * t[n] = correct self-loop term)
__global__ void agg2_warp_kernel(const float* __restrict__ b2, float* __restrict__ out) {
    int node = blockIdx.x * (blockDim.x >> 5) + (threadIdx.x >> 5);
    if (node >= NN) return;
    int lane = threadIdx.x & 31;

    int beg = g_rowptr[node], end = g_rowptr[node + 1];
    float a0 = 0.f, a1 = 0.f;
    for (int j = beg + lane; j < end; j += 32) {
        float2 tv = *(const float2*)&g_t[(size_t)g_col[j] * 2];
        a0 += tv.x;
        a1 += tv.y;
    }
    #pragma unroll
    for (int off = 16; off > 0; off >>= 1) {
        a0 += __shfl_xor_sync(0xffffffff, a0, off);
        a1 += __shfl_xor_sync(0xffffffff, a1, off);
    }
    if (lane == 0) {
        float di = g_dinv[node];
        float2 self = *(const float2*)&g_t[(size_t)node * 2];
        *(float2*)&out[(size_t)node * 2] =
            make_float2(di * (a0 + self.x) + b2[0], di * (a1 + self.y) + b2[1]);
    }
}

// ---------------- launch: gemm1 || CSR-build, then join ----------------
static inline void launch_csr_chain(cudaStream_t s, const int* src, const int* dst) {
    count_deg_kernel<<<(NE + 255) / 256, 256, 0, s>>>(dst);
    scan_lookback_kernel<<<SCAN_NBLK, 256, 0, s>>>();
    fill_csr_kernel<<<(NE + 255) / 256, 256, 0, s>>>(src, dst);
}

static inline void launch_gemm(const float* x, const float* W1) {
    if (g_tf32_ok)
        gemm1_tf32_kernel<<<GEMM_BLOCKS, 256, GEMM_SMEM_BYTES>>>(x, W1);
    else
        gemm1_kernel<<<GEMM_BLOCKS, 256>>>(x, W1);
}

extern "C" void kernel_launch(void* const* d_in, const int* in_sizes, int n_in,
                              void* d_out, int out_size) {
    const float* x  = (const float*)d_in[0];
    const int*   ei = (const int*)  d_in[1];
    const float* W1 = (const float*)d_in[2];
    const float* b1 = (const float*)d_in[3];
    const float* W2 = (const float*)d_in[4];
    const float* b2 = (const float*)d_in[5];
    float* out = (float*)d_out;

    const int* src = ei;
    const int* dst = ei + NE;

    if (g_side) {
        cudaEventRecord(g_evFork, 0);
        cudaStreamWaitEvent(g_side, g_evFork, 0);
        launch_csr_chain(g_side, src, dst);
        cudaEventRecord(g_evJoin, g_side);

        launch_gemm(x, W1);

        cudaStreamWaitEvent(0, g_evJoin, 0);
    } else {
        launch_gemm(x, W1);
        launch_csr_chain(0, src, dst);
    }

    agg1_fused_kernel<<<(NN + 7) / 8, 256>>>(b1, W2);
    agg2_warp_kernel<<<(NN + 7) / 8, 256>>>(b2, out);
}

// round 15
// speedup vs baseline: 1.3010x; 1.3010x over previous
#include <cuda_runtime.h>
#include <cuda_fp16.h>
#include <math.h>

#define NN 50000
#define NE 600000
#define FDIM 128
#define SCAN_EPB 1024
#define SCAN_NBLK ((NN + SCAN_EPB - 1) / SCAN_EPB)   // 49

#define GEMM_BLOCKS ((NN + 127) / 128)               // 391
#define SW_PITCH 136
#define SA_PITCH 68
#define GEMM_SMEM_BYTES ((128 * SW_PITCH + 128 * SA_PITCH) * 4)   // 104448

// ---------------- scratch (static device globals; zero-initialized) ----------------
// INVARIANT: g_deg and g_lb_flag are zero at kernel_launch entry; every launch
// restores them to zero (scan re-zeros deg after reading; fill re-zeros flags).
__device__ int     g_deg[NN + 4];
__device__ float   g_dinv[NN];
__device__ int     g_rowptr[NN + 1];
__device__ int     g_rank[NE];
__device__ int     g_col[NE];
__device__ int     g_lb_flag[SCAN_NBLK];
__device__ int     g_lb_agg [SCAN_NBLK];
__device__ int     g_lb_incl[SCAN_NBLK];
__device__ __half2 g_h1h[(size_t)NN * 64];    // h1 = x@W1 in fp16
__device__ float   g_t [(size_t)NN * 2];

// ---------------- cp.async helpers ----------------
__device__ __forceinline__ unsigned smem_addr_u32(const void* p) {
    unsigned a;
    asm("{ .reg .u64 t; cvta.to.shared.u64 t, %1; cvt.u32.u64 %0, t; }" : "=r"(a) : "l"(p));
    return a;
}
#define CP_ASYNC16(sa, gp) \
    asm volatile("cp.async.cg.shared.global [%0], [%1], 16;" :: "r"(sa), "l"(gp))
#define CP_COMMIT()  asm volatile("cp.async.commit_group;" ::: "memory")
#define CP_WAIT0()   asm volatile("cp.async.wait_group 0;" ::: "memory")

// ---------------- GEMM1 (tf32 tensor cores, cp.async loads): h1 = x @ W1 -> fp16 --------
// Raw fp32 lands in smem; mma.tf32 reads the top 19 bits (truncation rounding).
__global__ void __launch_bounds__(256, 2)
gemm1_tf32_kernel(const float* __restrict__ A, const float* __restrict__ W) {
    extern __shared__ float smem_f[];
    float* Ws = smem_f;                      // [128][SW_PITCH]
    float* As = smem_f + 128 * SW_PITCH;     // [128][SA_PITCH]

    const int tid  = threadIdx.x;
    const int lane = tid & 31;
    const int wid  = tid >> 5;
    const int g    = lane >> 2;
    const int t    = lane & 3;
    const int wm   = (wid & 3) * 32;
    const int wn   = (wid >> 2) * 64;
    const int block_row = blockIdx.x * 128;

    // async-load full W (128x128 fp32) and first A chunk together
    #pragma unroll
    for (int i = 0; i < 16; i++) {
        int idx  = tid + i * 256;           // 0..4095 float4 slots
        int row  = idx >> 5;
        int col4 = (idx & 31) * 4;
        CP_ASYNC16(smem_addr_u32(&Ws[row * SW_PITCH + col4]),
                   &W[(size_t)row * 128 + col4]);
    }

    float acc[2][8][4];
    #pragma unroll
    for (int mt = 0; mt < 2; mt++)
        #pragma unroll
        for (int j = 0; j < 8; j++)
            #pragma unroll
            for (int q = 0; q < 4; q++) acc[mt][j][q] = 0.f;

    #pragma unroll
    for (int kc = 0; kc < 2; kc++) {
        if (kc > 0) __syncthreads();            // protect As reuse
        // A chunk: rows block_row..+128, cols kc*64..+64
        #pragma unroll
        for (int i = 0; i < 8; i++) {
            int idx  = tid + i * 256;            // 0..2047 float4 slots
            int row  = idx >> 4;
            int col4 = (idx & 15) * 4;
            int grow = block_row + row;
            if (grow < NN) {
                CP_ASYNC16(smem_addr_u32(&As[row * SA_PITCH + col4]),
                           &A[(size_t)grow * 128 + kc * 64 + col4]);
            } else {
                *(float4*)&As[row * SA_PITCH + col4] = make_float4(0.f, 0.f, 0.f, 0.f);
            }
        }
        CP_COMMIT();
        CP_WAIT0();
        __syncthreads();

        #pragma unroll
        for (int kk = 0; kk < 8; kk++) {
            int k0 = kk * 8;
            unsigned a[2][4];
            #pragma unroll
            for (int mt = 0; mt < 2; mt++) {
                int r0 = wm + mt * 16;
                a[mt][0] = __float_as_uint(As[(r0 + g    ) * SA_PITCH + k0 + t    ]);
                a[mt][1] = __float_as_uint(As[(r0 + g + 8) * SA_PITCH + k0 + t    ]);
                a[mt][2] = __float_as_uint(As[(r0 + g    ) * SA_PITCH + k0 + t + 4]);
                a[mt][3] = __float_as_uint(As[(r0 + g + 8) * SA_PITCH + k0 + t + 4]);
            }
            #pragma unroll
            for (int j = 0; j < 8; j++) {
                int n0 = wn + j * 8;
                unsigned b0 = __float_as_uint(Ws[(kc * 64 + k0 + t    ) * SW_PITCH + n0 + g]);
                unsigned b1 = __float_as_uint(Ws[(kc * 64 + k0 + t + 4) * SW_PITCH + n0 + g]);
                #pragma unroll
                for (int mt = 0; mt < 2; mt++) {
                    asm volatile(
                        "mma.sync.aligned.m16n8k8.row.col.f32.tf32.tf32.f32 "
                        "{%0,%1,%2,%3}, {%4,%5,%6,%7}, {%8,%9}, {%0,%1,%2,%3};\n"
                        : "+f"(acc[mt][j][0]), "+f"(acc[mt][j][1]),
                          "+f"(acc[mt][j][2]), "+f"(acc[mt][j][3])
                        : "r"(a[mt][0]), "r"(a[mt][1]), "r"(a[mt][2]), "r"(a[mt][3]),
                          "r"(b0), "r"(b1));
                }
            }
        }
    }

    #pragma unroll
    for (int mt = 0; mt < 2; mt++) {
        #pragma unroll
        for (int j = 0; j < 8; j++) {
            int col = wn + j * 8 + 2 * t;
            int r0  = block_row + wm + mt * 16 + g;
            int r1  = r0 + 8;
            if (r0 < NN)
                g_h1h[(size_t)r0 * 64 + (col >> 1)] = __floats2half2_rn(acc[mt][j][0], acc[mt][j][1]);
            if (r1 < NN)
                g_h1h[(size_t)r1 * 64 + (col >> 1)] = __floats2half2_rn(acc[mt][j][2], acc[mt][j][3]);
        }
    }
}

// ---------------- fallback SIMT GEMM ----------------
__global__ void gemm1_kernel(const float* __restrict__ A, const float* __restrict__ W) {
    __shared__ float Asb[16][128];
    __shared__ float Bsb[16][128];
    const int block_row = blockIdx.x * 128;
    const int tid  = threadIdx.x;
    const int tcol = tid & 15;
    const int trow = tid >> 4;

    float acc[8][8];
    #pragma unroll
    for (int i = 0; i < 8; i++)
        #pragma unroll
        for (int j = 0; j < 8; j++) acc[i][j] = 0.f;

    for (int k0 = 0; k0 < 128; k0 += 16) {
        #pragma unroll
        for (int l = 0; l < 2; l++) {
            int f  = tid * 2 + l;
            int r  = f >> 2;
            int kq = (f & 3) * 4;
            int grow = block_row + r;
            float4 v = (grow < NN) ? *(const float4*)&A[(size_t)grow * 128 + k0 + kq]
                                   : make_float4(0.f, 0.f, 0.f, 0.f);
            Asb[kq + 0][r] = v.x; Asb[kq + 1][r] = v.y;
            Asb[kq + 2][r] = v.z; Asb[kq + 3][r] = v.w;
        }
        #pragma unroll
        for (int l = 0; l < 2; l++) {
            int f  = tid * 2 + l;
            int r  = f >> 5;
            int cq = (f & 31) * 4;
            *(float4*)&Bsb[r][cq] = *(const float4*)&W[(size_t)(k0 + r) * 128 + cq];
        }
        __syncthreads();
        #pragma unroll
        for (int kk = 0; kk < 16; kk++) {
            float a[8], b[8];
            #pragma unroll
            for (int i = 0; i < 8; i += 4) *(float4*)&a[i] = *(float4*)&Asb[kk][trow * 8 + i];
            #pragma unroll
            for (int j = 0; j < 8; j += 4) *(float4*)&b[j] = *(float4*)&Bsb[kk][tcol * 8 + j];
            #pragma unroll
            for (int i = 0; i < 8; i++)
                #pragma unroll
                for (int j = 0; j < 8; j++) acc[i][j] += a[i] * b[j];
        }
        __syncthreads();
    }
    #pragma unroll
    for (int i = 0; i < 8; i++) {
        int grow = block_row + trow * 8 + i;
        if (grow < NN) {
            #pragma unroll
            for (int j = 0; j < 8; j += 2)
                g_h1h[(size_t)grow * 64 + (tcol * 8 + j) / 2] =
                    __floats2half2_rn(acc[i][j], acc[i][j + 1]);
        }
    }
}

// ---------------- host-side stream/event + gemm config ----------
static cudaStream_t g_side = nullptr;
static cudaEvent_t  g_evFork = nullptr, g_evJoin = nullptr;
static bool g_tf32_ok = false;
namespace {
struct InitOnce {
    InitOnce() {
        if (cudaStreamCreateWithFlags(&g_side, cudaStreamNonBlocking) != cudaSuccess) g_side = nullptr;
        if (cudaEventCreateWithFlags(&g_evFork, cudaEventDisableTiming) != cudaSuccess) g_evFork = nullptr;
        if (cudaEventCreateWithFlags(&g_evJoin, cudaEventDisableTiming) != cudaSuccess) g_evJoin = nullptr;
        if (!g_evFork || !g_evJoin) g_side = nullptr;
        g_tf32_ok = (cudaFuncSetAttribute(gemm1_tf32_kernel,
                        cudaFuncAttributeMaxDynamicSharedMemorySize,
                        GEMM_SMEM_BYTES) == cudaSuccess);
    }
};
static InitOnce g_initOnce;
}

// ---------------- degree count + per-edge rank ----------------
__global__ void count_deg_kernel(const int* __restrict__ dst) {
    int e = blockIdx.x * blockDim.x + threadIdx.x;
    if (e < NE) g_rank[e] = atomicAdd(&g_deg[dst[e]], 1);
}

// ---------------- single-kernel decoupled-lookback scan (re-zeros g_deg) ----------------
__global__ void scan_lookback_kernel() {
    __shared__ int ws[8];
    __shared__ int s_tot;
    __shared__ int s_ex;
    const int tid  = threadIdx.x;
    const int lane = tid & 31, warp = tid >> 5;
    const int b    = blockIdx.x;
    const int base = b * SCAN_EPB + tid * 4;

    int4 v = make_int4(0, 0, 0, 0);
    if (base + 3 < NN) {
        v = *(const int4*)&g_deg[base];
        *(int4*)&g_deg[base] = make_int4(0, 0, 0, 0);
    } else {
        if (base     < NN) { v.x = g_deg[base];     g_deg[base]     = 0; }
        if (base + 1 < NN) { v.y = g_deg[base + 1]; g_deg[base + 1] = 0; }
        if (base + 2 < NN) { v.z = g_deg[base + 2]; g_deg[base + 2] = 0; }
        if (base + 3 < NN) { v.w = g_deg[base + 3]; g_deg[base + 3] = 0; }
    }
    int s = v.x + v.y + v.z + v.w;

    int sc = s;
    #pragma unroll
    for (int off = 1; off < 32; off <<= 1) {
        int n = __shfl_up_sync(0xffffffff, sc, off);
        if (lane >= off) sc += n;
    }
    if (lane == 31) ws[warp] = sc;
    __syncthreads();
    if (warp == 0 && lane < 8) {
        int wv = ws[lane];
        int wsc = wv;
        #pragma unroll
        for (int off = 1; off < 8; off <<= 1) {
            int n = __shfl_up_sync(0x000000ff, wsc, off);
            if (lane >= off) wsc += n;
        }
        if (lane == 7) s_tot = wsc;
        ws[lane] = wsc - wv;
    }
    __syncthreads();
    int ex_local = (sc - s) + ws[warp];
    int tot = s_tot;

    if (tid == 0) {
        g_lb_agg[b] = tot;
        __threadfence();
        if (b == 0) {
            g_lb_incl[0] = tot;
            __threadfence();
            *(volatile int*)&g_lb_flag[0] = 2;
            s_ex = 0;
            g_rowptr[0] = 0;
        } else {
            *(volatile int*)&g_lb_flag[b] = 1;
        }
    }

    if (b > 0 && warp == 0) {
        int ex = 0;
        int base_p = b - 1;
        while (true) {
            int p = base_p - lane;
            int f = 0, val = 0;
            if (p >= 0) {
                volatile int* fp = (volatile int*)&g_lb_flag[p];
                do { f = *fp; } while (f == 0);
                __threadfence();
                val = (f == 2) ? *(volatile int*)&g_lb_incl[p]
                               : *(volatile int*)&g_lb_agg[p];
            }
            unsigned m2 = __ballot_sync(0xffffffff, (p >= 0) && (f == 2));
            if (m2) {
                int stop = __ffs(m2) - 1;
                int contrib = (lane <= stop) ? val : 0;
                #pragma unroll
                for (int off = 16; off > 0; off >>= 1)
                    contrib += __shfl_xor_sync(0xffffffff, contrib, off);
                ex += contrib;
                break;
            } else {
                int contrib = (p >= 0) ? val : 0;
                #pragma unroll
                for (int off = 16; off > 0; off >>= 1)
                    contrib += __shfl_xor_sync(0xffffffff, contrib, off);
                ex += contrib;
                base_p -= 32;
                if (base_p < 0) break;
            }
        }
        if (lane == 0) {
            g_lb_incl[b] = ex + tot;
            __threadfence();
            *(volatile int*)&g_lb_flag[b] = 2;
            s_ex = ex;
        }
    }
    __syncthreads();

    int run = s_ex + ex_local;
    #pragma unroll
    for (int j = 0; j < 4; j++) {
        int idx = base + j;
        if (idx < NN) {
            int d = (j == 0) ? v.x : (j == 1) ? v.y : (j == 2) ? v.z : v.w;
            g_dinv[idx] = rsqrtf((float)(d + 1));
            run += d;
            g_rowptr[idx + 1] = run;
        }
    }
}

// ---------------- CSR fill (atomic-free) + flag re-zero ----------------
__global__ void fill_csr_kernel(const int* __restrict__ src, const int* __restrict__ dst) {
    int e = blockIdx.x * blockDim.x + threadIdx.x;
    if (e < NE) {
        int d = dst[e];
        g_col[g_rowptr[d] + g_rank[e]] = src[e];
    }
    if (blockIdx.x == 0 && threadIdx.x < SCAN_NBLK) g_lb_flag[threadIdx.x] = 0;
}

// ---------------- Fused layer-1 agg + bias + relu + W2 (R8 4-deep form) ----------------
__global__ void agg1_fused_kernel(const float* __restrict__ b1, const float* __restrict__ W2) {
    __shared__ float sW2[256];
    __shared__ float sb1[128];
    for (int i = threadIdx.x; i < 256; i += blockDim.x) sW2[i] = W2[i];
    for (int i = threadIdx.x; i < 128; i += blockDim.x) sb1[i] = b1[i];
    __syncthreads();

    int node = blockIdx.x * (blockDim.x >> 5) + (threadIdx.x >> 5);
    if (node >= NN) return;
    int lane = threadIdx.x & 31;

    float di = g_dinv[node];
    float w0 = di * di;

    uint2 raw = *(const uint2*)&g_h1h[(size_t)node * 64 + lane * 2];
    float2 f0 = __half22float2(*(__half2*)&raw.x);
    float2 f1 = __half22float2(*(__half2*)&raw.y);
    float4 acc = make_float4(f0.x * w0, f0.y * w0, f1.x * w0, f1.y * w0);

    int beg = g_rowptr[node], end = g_rowptr[node + 1];
    int j = beg;
    for (; j + 3 < end; j += 4) {
        int   c[4];
        float w[4];
        uint2 r[4];
        #pragma unroll
        for (int q = 0; q < 4; q++) c[q] = g_col[j + q];
        #pragma unroll
        for (int q = 0; q < 4; q++) w[q] = g_dinv[c[q]] * di;
        #pragma unroll
        for (int q = 0; q < 4; q++) r[q] = *(const uint2*)&g_h1h[(size_t)c[q] * 64 + lane * 2];
        #pragma unroll
        for (int q = 0; q < 4; q++) {
            float2 a0 = __half22float2(*(__half2*)&r[q].x);
            float2 a1 = __half22float2(*(__half2*)&r[q].y);
            acc.x += w[q] * a0.x; acc.y += w[q] * a0.y;
            acc.z += w[q] * a1.x; acc.w += w[q] * a1.y;
        }
    }
    for (; j < end; j++) {
        int s0 = g_col[j];
        float wA = g_dinv[s0] * di;
        uint2 rA = *(const uint2*)&g_h1h[(size_t)s0 * 64 + lane * 2];
        float2 a0 = __half22float2(*(__half2*)&rA.x);
        float2 a1 = __half22float2(*(__half2*)&rA.y);
        acc.x += wA * a0.x; acc.y += wA * a0.y;
        acc.z += wA * a1.x; acc.w += wA * a1.y;
    }

    int c = lane * 4;
    acc.x = fmaxf(acc.x + sb1[c + 0], 0.f);
    acc.y = fmaxf(acc.y + sb1[c + 1], 0.f);
    acc.z = fmaxf(acc.z + sb1[c + 2], 0.f);
    acc.w = fmaxf(acc.w + sb1[c + 3], 0.f);

    float t0 = acc.x * sW2[(c + 0) * 2 + 0] + acc.y * sW2[(c + 1) * 2 + 0]
             + acc.z * sW2[(c + 2) * 2 + 0] + acc.w * sW2[(c + 3) * 2 + 0];
    float t1 = acc.x * sW2[(c + 0) * 2 + 1] + acc.y * sW2[(c + 1) * 2 + 1]
             + acc.z * sW2[(c + 2) * 2 + 1] + acc.w * sW2[(c + 3) * 2 + 1];
    #pragma unroll
    for (int off = 16; off > 0; off >>= 1) {
        t0 += __shfl_xor_sync(0xffffffff, t0, off);
        t1 += __shfl_xor_sync(0xffffffff, t1, off);
    }
    if (lane == 0) {
        *(float2*)&g_t[(size_t)node * 2] = make_float2(t0, t1);
    }
}

// ---------------- Layer-2 aggregation: thread per node (R8 form) ----------------
__global__ void agg2_kernel(const float* __restrict__ b2, float* __restrict__ out) {
    int i = blockIdx.x * blockDim.x + threadIdx.x;
    if (i >= NN) return;
    float di = g_dinv[i];
    float w0 = di * di;
    float2 tv = *(const float2*)&g_t[(size_t)i * 2];
    float a0 = w0 * tv.x;
    float a1 = w0 * tv.y;
    int beg = g_rowptr[i], end = g_rowptr[i + 1];
    int j = beg;
    for (; j + 3 < end; j += 4) {
        int    c[4];
        float  w[4];
        float2 r[4];
        #pragma unroll
        for (int q = 0; q < 4; q++) c[q] = g_col[j + q];
        #pragma unroll
        for (int q = 0; q < 4; q++) w[q] = g_dinv[c[q]] * di;
        #pragma unroll
        for (int q = 0; q < 4; q++) r[q] = *(const float2*)&g_t[(size_t)c[q] * 2];
        #pragma unroll
        for (int q = 0; q < 4; q++) { a0 += w[q] * r[q].x; a1 += w[q] * r[q].y; }
    }
    for (; j < end; j++) {
        int s = g_col[j];
        float w = g_dinv[s] * di;
        float2 sv = *(const float2*)&g_t[(size_t)s * 2];
        a0 += w * sv.x;
        a1 += w * sv.y;
    }
    *(float2*)&out[(size_t)i * 2] = make_float2(a0 + b2[0], a1 + b2[1]);
}

// ---------------- launch: gemm1 || CSR-build, then join ----------------
static inline void launch_csr_chain(cudaStream_t s, const int* src, const int* dst) {
    count_deg_kernel<<<(NE + 255) / 256, 256, 0, s>>>(dst);
    scan_lookback_kernel<<<SCAN_NBLK, 256, 0, s>>>();
    fill_csr_kernel<<<(NE + 255) / 256, 256, 0, s>>>(src, dst);
}

static inline void launch_gemm(const float* x, const float* W1) {
    if (g_tf32_ok)
        gemm1_tf32_kernel<<<GEMM_BLOCKS, 256, GEMM_SMEM_BYTES>>>(x, W1);
    else
        gemm1_kernel<<<GEMM_BLOCKS, 256>>>(x, W1);
}

extern "C" void kernel_launch(void* const* d_in, const int* in_sizes, int n_in,
                              void* d_out, int out_size) {
    const float* x  = (const float*)d_in[0];
    const int*   ei = (const int*)  d_in[1];
    const float* W1 = (const float*)d_in[2];
    const float* b1 = (const float*)d_in[3];
    const float* W2 = (const float*)d_in[4];
    const float* b2 = (const float*)d_in[5];
    float* out = (float*)d_out;

    const int* src = ei;
    const int* dst = ei + NE;

    if (g_side) {
        cudaEventRecord(g_evFork, 0);
        cudaStreamWaitEvent(g_side, g_evFork, 0);
        launch_csr_chain(g_side, src, dst);
        cudaEventRecord(g_evJoin, g_side);

        launch_gemm(x, W1);

        cudaStreamWaitEvent(0, g_evJoin, 0);
    } else {
        launch_gemm(x, W1);
        launch_csr_chain(0, src, dst);
    }

    agg1_fused_kernel<<<(NN + 7) / 8, 256>>>(b1, W2);
    agg2_kernel<<<(NN + 255) / 256, 256>>>(b2, out);
}